// round 16
// baseline (speedup 1.0000x reference)
#include <cuda_runtime.h>
#include <cuda_bf16.h>
#include <math.h>
#include <stdint.h>

typedef __nv_bfloat16 bf16;

// Problem constants (B=2, H=W=256, C=256, NH=8, WS=8, SHIFT=4)
#define MTOK   131072
#define CD     256
#define NWIN   2048
#define HIDDEN 1024

// ---------------- static scratch ----------------
__device__ __align__(16) bf16  g_h   [(size_t)MTOK * CD];       // LN1 out (bf16 GEMM A)
__device__ __align__(16) bf16  g_qkvb[(size_t)MTOK * 768];      // fused QKV out (bf16)
__device__ float g_att [(size_t)MTOK * CD];                     // attn out
__device__ float g_y2f [(size_t)MTOK * CD];                     // LN2 out fp32 (residual)
__device__ __align__(16) bf16  g_y2b [(size_t)MTOK * CD];       // LN2 out bf16 (GEMM A)
__device__ __align__(16) bf16  g_u   [(size_t)MTOK * HIDDEN];   // fc1+gelu out (bf16)
__device__ __align__(16) bf16 g_wt_qkv[768 * 256];
__device__ __align__(16) bf16 g_wt_f1 [1024 * 256];
__device__ __align__(16) bf16 g_wt_f2 [256 * 1024];
__device__ float g_bqkv[768];

__device__ __forceinline__ uint32_t pkbf(float a, float b) {
    __nv_bfloat162 t = __floats2bfloat162_rn(a, b);
    return reinterpret_cast<uint32_t&>(t);
}
__device__ __forceinline__ uint32_t smem_u32(const void* p) {
    return (uint32_t)__cvta_generic_to_shared(p);
}

// ---------------- single weight-pack kernel (transposes + bias), 705 blocks --------------
__device__ __forceinline__ void tr_tile(const float* __restrict__ src, bf16* __restrict__ dst,
                                        int R, int Cc, int bx, int by) {
    __shared__ float t[32][33];
    int x = bx * 32 + threadIdx.x;
#pragma unroll
    for (int i = 0; i < 32; i += 8) {
        int y = by * 32 + threadIdx.y + i;
        t[threadIdx.y + i][threadIdx.x] = src[(size_t)y * Cc + x];
    }
    __syncthreads();
    int x2 = by * 32 + threadIdx.x;
#pragma unroll
    for (int i = 0; i < 32; i += 8) {
        int y2 = bx * 32 + threadIdx.y + i;
        dst[(size_t)y2 * R + x2] = __float2bfloat16_rn(t[threadIdx.x][threadIdx.y + i]);
    }
}

__global__ void pack_all(const float* __restrict__ wq, const float* __restrict__ wk,
                         const float* __restrict__ wv, const float* __restrict__ wf1,
                         const float* __restrict__ wf2,
                         const float* __restrict__ bq, const float* __restrict__ bk,
                         const float* __restrict__ bv,
                         bf16* __restrict__ wtqkv, bf16* __restrict__ wtf1,
                         bf16* __restrict__ wtf2, float* __restrict__ bqkv) {
    int b = blockIdx.x;
    if (b < 64) {
        tr_tile(wq, wtqkv, 256, 256, b & 7, b >> 3);
    } else if (b < 128) {
        int t = b - 64;  tr_tile(wk, wtqkv + 65536, 256, 256, t & 7, t >> 3);
    } else if (b < 192) {
        int t = b - 128; tr_tile(wv, wtqkv + 131072, 256, 256, t & 7, t >> 3);
    } else if (b < 448) {
        int t = b - 192; tr_tile(wf1, wtf1, 256, 1024, t & 31, t >> 5);
    } else if (b < 704) {
        int t = b - 448; tr_tile(wf2, wtf2, 1024, 256, t & 7, t >> 3);
    } else {
        int t = threadIdx.y * 32 + threadIdx.x;
        bqkv[t]       = bq[t];
        bqkv[256 + t] = bk[t];
        bqkv[512 + t] = bv[t];
    }
}

// ---------------- warp-level dual reduction ----------------
__device__ __forceinline__ void warpReduce2(float& a, float& b) {
#pragma unroll
    for (int o = 16; o; o >>= 1) {
        a += __shfl_xor_sync(0xffffffffu, a, o);
        b += __shfl_xor_sync(0xffffffffu, b, o);
    }
}

// ---------------- kernel 1: LN1 + shift-roll + window partition (warp/row, bf16 out) -----
__global__ void ln1_window_kernel(const float* __restrict__ x,
                                  const float* __restrict__ g1,
                                  const float* __restrict__ b1,
                                  bf16* __restrict__ h) {
    int m = blockIdx.x * 8 + (threadIdx.x >> 5);
    int lane = threadIdx.x & 31;
    int bw = m >> 6, n = m & 63;
    int bb = bw >> 10, widx = bw & 1023;
    int wh = widx >> 5, ww = widx & 31;
    int r = n >> 3, c = n & 7;
    int gh = (wh * 8 + r + 4) & 255;
    int gw = (ww * 8 + c + 4) & 255;
    const float* row = x + ((size_t)bb * 65536 + (size_t)gh * 256 + gw) * CD;
    int ch = lane * 8;
    float4 v0 = *(const float4*)(row + ch);
    float4 v1 = *(const float4*)(row + ch + 4);
    float a = v0.x + v0.y + v0.z + v0.w + v1.x + v1.y + v1.z + v1.w;
    float b = v0.x * v0.x + v0.y * v0.y + v0.z * v0.z + v0.w * v0.w
            + v1.x * v1.x + v1.y * v1.y + v1.z * v1.z + v1.w * v1.w;
    warpReduce2(a, b);
    float mu = a * (1.0f / CD);
    float rstd = rsqrtf(b * (1.0f / CD) - mu * mu + 1e-5f);
    float4 ga = *(const float4*)(g1 + ch);
    float4 gb = *(const float4*)(g1 + ch + 4);
    float4 ba = *(const float4*)(b1 + ch);
    float4 bbv = *(const float4*)(b1 + ch + 4);
    uint4 st;
    st.x = pkbf((v0.x - mu) * rstd * ga.x + ba.x,  (v0.y - mu) * rstd * ga.y + ba.y);
    st.y = pkbf((v0.z - mu) * rstd * ga.z + ba.z,  (v0.w - mu) * rstd * ga.w + ba.w);
    st.z = pkbf((v1.x - mu) * rstd * gb.x + bbv.x, (v1.y - mu) * rstd * gb.y + bbv.y);
    st.w = pkbf((v1.z - mu) * rstd * gb.z + bbv.z, (v1.w - mu) * rstd * gb.w + bbv.w);
    *(uint4*)(h + (size_t)m * CD + ch) = st;
}

// ---------------- mma/ldmatrix primitives ----------------
__device__ __forceinline__ void ldsm4(uint32_t& r0, uint32_t& r1, uint32_t& r2, uint32_t& r3,
                                      uint32_t addr) {
    asm volatile("ldmatrix.sync.aligned.m8n8.x4.shared.b16 {%0,%1,%2,%3}, [%4];"
                 : "=r"(r0), "=r"(r1), "=r"(r2), "=r"(r3) : "r"(addr));
}
__device__ __forceinline__ void ldsm4t(uint32_t& r0, uint32_t& r1, uint32_t& r2, uint32_t& r3,
                                       uint32_t addr) {
    asm volatile("ldmatrix.sync.aligned.m8n8.x4.trans.shared.b16 {%0,%1,%2,%3}, [%4];"
                 : "=r"(r0), "=r"(r1), "=r"(r2), "=r"(r3) : "r"(addr));
}
__device__ __forceinline__ void mma_bf16(float* c, const uint32_t* a, const uint32_t* b) {
    asm volatile(
        "mma.sync.aligned.m16n8k16.row.col.f32.bf16.bf16.f32 "
        "{%0,%1,%2,%3}, {%4,%5,%6,%7}, {%8,%9}, {%0,%1,%2,%3};"
        : "+f"(c[0]), "+f"(c[1]), "+f"(c[2]), "+f"(c[3])
        : "r"(a[0]), "r"(a[1]), "r"(a[2]), "r"(a[3]), "r"(b[0]), "r"(b[1]));
}
#define CP_COMMIT() asm volatile("cp.async.commit_group;")

// ---------------- bf16 tensor-core GEMM: 128 thr, warp 64x64, BK=32, 4-stage ------------
#define ROWB2 80                        // 64B data + 16B pad: conflict-free LDSM
#define OPB2  (128 * ROWB2)             // 10240 per operand per stage
#define STG2  (2 * OPB2)                // 20480 per stage
#define STAGES2 4
#define SMEM2 (STAGES2 * STG2)          // 81920

__device__ __forceinline__ void fill_stage2(uint32_t sA, uint32_t sB,
                                            const bf16* __restrict__ A,
                                            const bf16* __restrict__ Bt,
                                            int m0, int n0, int K, int k0, int tid) {
#pragma unroll
    for (int i = 0; i < 4; i++) {
        int idx = tid + 128 * i;                 // 0..511
        int rm = idx >> 2, g = idx & 3;          // row, 16B chunk
        uint32_t doff = (uint32_t)(rm * ROWB2 + g * 16);
        const bf16* ga = A + (size_t)(m0 + rm) * K + k0 + g * 8;
        asm volatile("cp.async.cg.shared.global [%0], [%1], 16;" :: "r"(sA + doff), "l"(ga));
        const bf16* gb = Bt + (size_t)(n0 + rm) * K + k0 + g * 8;
        asm volatile("cp.async.cg.shared.global [%0], [%1], 16;" :: "r"(sB + doff), "l"(gb));
    }
}

// C[M,Nn] = A[M,K] @ Bt[Nn,K]^T + bias (+GELU / +res). BM=BN=128, BK=32, 4 warps 2m x 2n.
template <bool GELU, bool RES, bool OUTBF>
__global__ void __launch_bounds__(128, 2)
tgemm(const bf16* __restrict__ A, const bf16* __restrict__ Bt,
      const float* __restrict__ bias, const float* __restrict__ res,
      void* __restrict__ Cout, int M, int Nn, int K) {
    extern __shared__ __align__(16) char smem[];
    int tid = threadIdx.x;
    int lane = tid & 31, wid = tid >> 5;
    int wm = wid >> 1, wn = wid & 1;             // warp tile: rows wm*64, cols wn*64
    int m0 = blockIdx.y * 128, n0 = blockIdx.x * 128;
    uint32_t base = (uint32_t)__cvta_generic_to_shared(smem);

    float acc[4][8][4] = {};
    const int NITER = K >> 5;

#pragma unroll
    for (int s = 0; s < STAGES2 - 1; s++) {
        if (s < NITER) {
            uint32_t sA = base + s * STG2;
            fill_stage2(sA, sA + OPB2, A, Bt, m0, n0, K, s * 32, tid);
        }
        CP_COMMIT();
    }

    int l7 = lane & 7, lh = (lane >> 3) & 1, ls = lane >> 4;
    for (int it = 0; it < NITER; it++) {
        asm volatile("cp.async.wait_group %0;" :: "n"(STAGES2 - 2));
        __syncthreads();

        int nxt = it + STAGES2 - 1;
        if (nxt < NITER) {
            uint32_t sA = base + (nxt % STAGES2) * STG2;
            fill_stage2(sA, sA + OPB2, A, Bt, m0, n0, K, nxt * 32, tid);
        }
        CP_COMMIT();

        uint32_t sA = base + (it % STAGES2) * STG2;
        uint32_t sB = sA + OPB2;
#pragma unroll
        for (int kk = 0; kk < 2; kk++) {         // 2 x k16 per BK=32
            uint32_t af[4][4];
#pragma unroll
            for (int mt = 0; mt < 4; mt++) {
                int row = wm * 64 + mt * 16 + l7 + lh * 8;
                ldsm4(af[mt][0], af[mt][1], af[mt][2], af[mt][3],
                      sA + (uint32_t)(row * ROWB2 + kk * 32 + ls * 16));
            }
            uint32_t bfr[4][4];
#pragma unroll
            for (int p = 0; p < 4; p++) {
                int row = wn * 64 + p * 16 + l7 + ls * 8;
                ldsm4(bfr[p][0], bfr[p][1], bfr[p][2], bfr[p][3],
                      sB + (uint32_t)(row * ROWB2 + kk * 32 + lh * 16));
            }
#pragma unroll
            for (int mt = 0; mt < 4; mt++)
#pragma unroll
                for (int p = 0; p < 4; p++) {
                    mma_bf16(acc[mt][2 * p],     af[mt], &bfr[p][0]);
                    mma_bf16(acc[mt][2 * p + 1], af[mt], &bfr[p][2]);
                }
        }
        __syncthreads();
    }

    int r0 = lane >> 2, c0 = (lane & 3) << 1;
#pragma unroll
    for (int mt = 0; mt < 4; mt++) {
#pragma unroll
        for (int half = 0; half < 2; half++) {
            int row = m0 + wm * 64 + mt * 16 + half * 8 + r0;
#pragma unroll
            for (int nt = 0; nt < 8; nt++) {
                int col = n0 + wn * 64 + ((nt >> 1) << 4) + ((nt & 1) << 3) + c0;
                float v0 = acc[mt][nt][half * 2 + 0] + bias[col];
                float v1 = acc[mt][nt][half * 2 + 1] + bias[col + 1];
                if (GELU) {
                    v0 = 0.5f * v0 * (1.0f + erff(v0 * 0.70710678118654752f));
                    v1 = 0.5f * v1 * (1.0f + erff(v1 * 0.70710678118654752f));
                }
                if (RES) {
                    v0 += res[(size_t)row * Nn + col];
                    v1 += res[(size_t)row * Nn + col + 1];
                }
                if (OUTBF) {
                    *(uint32_t*)((bf16*)Cout + (size_t)row * Nn + col) = pkbf(v0, v1);
                } else {
                    *(float2*)((float*)Cout + (size_t)row * Nn + col) = make_float2(v0, v1);
                }
            }
        }
    }
}

// ---------------- kernel 3: tensor-core windowed attention ----------------
// block = (window, 2-head group), 256 threads = 8 warps; warp = (head, 16-row Q quarter)
__global__ void __launch_bounds__(256, 3)
attn_mma(const bf16* __restrict__ qkv, const float* __restrict__ bias_table,
         float* __restrict__ attn_out) {
    __shared__ __align__(16) bf16 sQ[2][64][40];   // 80B rows: conflict-free LDSM
    __shared__ __align__(16) bf16 sK[2][64][40];
    __shared__ __align__(16) bf16 sV[2][64][40];
    __shared__ float sbias[1800];                   // 225 x 8
    __shared__ int   lab[64];

    int tid = threadIdx.x;
    int bw = blockIdx.x >> 2, hg = blockIdx.x & 3;  // head group: heads hg*2, hg*2+1
    int widx = bw & 1023;
    int wh = widx >> 5, ww = widx & 31;

#pragma unroll
    for (int i = 0; i < 6; i++) {
        int idx = tid + 256 * i;                    // 0..1535
        int nm = idx >> 3;
        int hc = idx & 7;
        int n = nm / 3, m = nm - 3 * n;
        const bf16* src = qkv + (size_t)(bw * 64 + n) * 768 + m * 256 + hg * 64 + hc * 8;
        uint4 val = *(const uint4*)src;
        bf16* dst = (m == 0 ? &sQ[0][0][0] : (m == 1 ? &sK[0][0][0] : &sV[0][0][0]));
        int h = hc >> 2, c = hc & 3;
        *(uint4*)(dst + (h * 64 + n) * 40 + c * 8) = val;
    }
    for (int j = tid; j < 1800; j += 256) sbias[j] = bias_table[j];
    if (tid < 64) {
        int ri2 = tid >> 3, ci2 = tid & 7;
        int srow = wh * 8 + ri2, scol = ww * 8 + ci2;
        int lh2 = (srow < 248) ? 0 : ((srow < 252) ? 1 : 2);
        int lw2 = (scol < 248) ? 0 : ((scol < 252) ? 1 : 2);
        lab[tid] = lh2 * 3 + lw2;
    }
    __syncthreads();

    int lane = tid & 31, wid = tid >> 5;
    int h = wid & 1, mq = wid >> 1;
    int m0 = mq * 16;
    int headg = hg * 2 + h;
    const bf16* Qh = &sQ[h][0][0];
    const bf16* Kh = &sK[h][0][0];
    const bf16* Vh = &sV[h][0][0];

    uint32_t aq[2][4];
    {
        int row = m0 + (lane & 15);
        int col = (lane >> 4) * 8;
#pragma unroll
        for (int kt = 0; kt < 2; kt++)
            ldsm4(aq[kt][0], aq[kt][1], aq[kt][2], aq[kt][3],
                  smem_u32(Qh + row * 40 + kt * 16 + col));
    }

    float S[8][4] = {};
    {
        int rofs = (lane & 7) + ((lane & 16) ? 8 : 0);
        int cofs = (lane & 8) ? 8 : 0;
#pragma unroll
        for (int nj = 0; nj < 4; nj++) {
#pragma unroll
            for (int dh = 0; dh < 2; dh++) {
                uint32_t kb[4];
                ldsm4(kb[0], kb[1], kb[2], kb[3],
                      smem_u32(Kh + (16 * nj + rofs) * 40 + dh * 16 + cofs));
                mma_bf16(S[2 * nj],     aq[dh], &kb[0]);
                mma_bf16(S[2 * nj + 1], aq[dh], &kb[2]);
            }
        }
    }

    const float sscale = 0.17677669529663687f;
    int g = lane >> 2, t = lane & 3;
    int i0 = m0 + g;
    int li[2] = { lab[i0], lab[i0 + 8] };
    int ri[2] = { i0 >> 3, (i0 + 8) >> 3 };
    int ci = i0 & 7;
#pragma unroll
    for (int n8 = 0; n8 < 8; n8++) {
#pragma unroll
        for (int e = 0; e < 4; e++) {
            int half = e >> 1;
            int j = n8 * 8 + t * 2 + (e & 1);
            int rj = j >> 3, cj = j & 7;
            int rel = (ri[half] - rj + 7) * 15 + (ci - cj + 7);
            float s = S[n8][e] * sscale + sbias[rel * 8 + headg];
            if (li[half] != lab[j]) s -= 100.0f;
            S[n8][e] = s;
        }
    }

    float mx0 = -1e30f, mx1 = -1e30f;
#pragma unroll
    for (int n8 = 0; n8 < 8; n8++) {
        mx0 = fmaxf(mx0, fmaxf(S[n8][0], S[n8][1]));
        mx1 = fmaxf(mx1, fmaxf(S[n8][2], S[n8][3]));
    }
    mx0 = fmaxf(mx0, __shfl_xor_sync(0xffffffffu, mx0, 1));
    mx0 = fmaxf(mx0, __shfl_xor_sync(0xffffffffu, mx0, 2));
    mx1 = fmaxf(mx1, __shfl_xor_sync(0xffffffffu, mx1, 1));
    mx1 = fmaxf(mx1, __shfl_xor_sync(0xffffffffu, mx1, 2));
    float s0 = 0.f, s1 = 0.f;
#pragma unroll
    for (int n8 = 0; n8 < 8; n8++) {
        S[n8][0] = __expf(S[n8][0] - mx0); s0 += S[n8][0];
        S[n8][1] = __expf(S[n8][1] - mx0); s0 += S[n8][1];
        S[n8][2] = __expf(S[n8][2] - mx1); s1 += S[n8][2];
        S[n8][3] = __expf(S[n8][3] - mx1); s1 += S[n8][3];
    }
    s0 += __shfl_xor_sync(0xffffffffu, s0, 1);
    s0 += __shfl_xor_sync(0xffffffffu, s0, 2);
    s1 += __shfl_xor_sync(0xffffffffu, s1, 1);
    s1 += __shfl_xor_sync(0xffffffffu, s1, 2);
    float inv0 = 1.0f / s0, inv1 = 1.0f / s1;
#pragma unroll
    for (int n8 = 0; n8 < 8; n8++) {
        S[n8][0] *= inv0; S[n8][1] *= inv0;
        S[n8][2] *= inv1; S[n8][3] *= inv1;
    }

    float O[4][4] = {};
    {
        int rofs2 = (lane & 7) + ((lane & 8) ? 8 : 0);
        int cofs2 = (lane & 16) ? 8 : 0;
#pragma unroll
        for (int kt = 0; kt < 4; kt++) {
            uint32_t pa[4];
            pa[0] = pkbf(S[2 * kt][0],     S[2 * kt][1]);
            pa[1] = pkbf(S[2 * kt][2],     S[2 * kt][3]);
            pa[2] = pkbf(S[2 * kt + 1][0], S[2 * kt + 1][1]);
            pa[3] = pkbf(S[2 * kt + 1][2], S[2 * kt + 1][3]);
#pragma unroll
            for (int dh = 0; dh < 2; dh++) {
                uint32_t vb[4];
                ldsm4t(vb[0], vb[1], vb[2], vb[3],
                       smem_u32(Vh + (16 * kt + rofs2) * 40 + dh * 16 + cofs2));
                mma_bf16(O[dh * 2],     pa, &vb[0]);
                mma_bf16(O[dh * 2 + 1], pa, &vb[2]);
            }
        }
    }

    size_t base = ((size_t)(bw * 8 + headg) * 64) * 32;
#pragma unroll
    for (int dn = 0; dn < 4; dn++) {
        int d = dn * 8 + t * 2;
        *(float2*)&attn_out[base + (size_t)i0 * 32 + d]       = make_float2(O[dn][0], O[dn][1]);
        *(float2*)&attn_out[base + (size_t)(i0 + 8) * 32 + d] = make_float2(O[dn][2], O[dn][3]);
    }
}

// ---------------- kernel 4: un-window + un-roll + residual + LN2 (warp/row) -------------
__global__ void unwin_res_ln2(const float* __restrict__ x, const float* __restrict__ att,
                              const float* __restrict__ g2, const float* __restrict__ b2,
                              float* __restrict__ y2f, bf16* __restrict__ y2b) {
    int m = blockIdx.x * 8 + (threadIdx.x >> 5);
    int lane = threadIdx.x & 31;
    int bb = m >> 16, l = m & 65535;
    int gh = l >> 8, gw = l & 255;
    int sh = (gh + 252) & 255, sw = (gw + 252) & 255;
    int wh = sh >> 3, r = sh & 7, ww = sw >> 3, c = sw & 7;
    size_t base = ((size_t)((bb * 1024 + wh * 32 + ww) * 8 + r) * 64 + (size_t)c * 8) * 32;
    int ch = lane * 8;
    const float* xr = x + (size_t)m * CD + ch;
    const float* ar = att + base + ch;
    float4 x0 = *(const float4*)xr;
    float4 x1 = *(const float4*)(xr + 4);
    float4 a0 = *(const float4*)ar;
    float4 a1 = *(const float4*)(ar + 4);
    float4 v0 = {x0.x + a0.x, x0.y + a0.y, x0.z + a0.z, x0.w + a0.w};
    float4 v1 = {x1.x + a1.x, x1.y + a1.y, x1.z + a1.z, x1.w + a1.w};
    float a = v0.x + v0.y + v0.z + v0.w + v1.x + v1.y + v1.z + v1.w;
    float b = v0.x * v0.x + v0.y * v0.y + v0.z * v0.z + v0.w * v0.w
            + v1.x * v1.x + v1.y * v1.y + v1.z * v1.z + v1.w * v1.w;
    warpReduce2(a, b);
    float mu = a * (1.0f / CD);
    float rstd = rsqrtf(b * (1.0f / CD) - mu * mu + 1e-5f);
    float4 ga = *(const float4*)(g2 + ch);
    float4 gb = *(const float4*)(g2 + ch + 4);
    float4 ba = *(const float4*)(b2 + ch);
    float4 bbv = *(const float4*)(b2 + ch + 4);
    float4 o0, o1;
    o0.x = (v0.x - mu) * rstd * ga.x + ba.x;
    o0.y = (v0.y - mu) * rstd * ga.y + ba.y;
    o0.z = (v0.z - mu) * rstd * ga.z + ba.z;
    o0.w = (v0.w - mu) * rstd * ga.w + ba.w;
    o1.x = (v1.x - mu) * rstd * gb.x + bbv.x;
    o1.y = (v1.y - mu) * rstd * gb.y + bbv.y;
    o1.z = (v1.z - mu) * rstd * gb.z + bbv.z;
    o1.w = (v1.w - mu) * rstd * gb.w + bbv.w;
    float* dstf = y2f + (size_t)m * CD + ch;
    *(float4*)dstf = o0;
    *(float4*)(dstf + 4) = o1;
    uint4 st = { pkbf(o0.x, o0.y), pkbf(o0.z, o0.w), pkbf(o1.x, o1.y), pkbf(o1.z, o1.w) };
    *(uint4*)(y2b + (size_t)m * CD + ch) = st;
}

// ---------------- host launch ----------------
extern "C" void kernel_launch(void* const* d_in, const int* in_sizes, int n_in,
                              void* d_out, int out_size) {
    (void)in_sizes; (void)n_in; (void)out_size;
    const float* x    = (const float*)d_in[0];
    const float* g1   = (const float*)d_in[1];
    const float* b1   = (const float*)d_in[2];
    const float* wq   = (const float*)d_in[3];
    const float* bq   = (const float*)d_in[4];
    const float* wk   = (const float*)d_in[5];
    const float* bk   = (const float*)d_in[6];
    const float* wv   = (const float*)d_in[7];
    const float* bv   = (const float*)d_in[8];
    const float* tbl  = (const float*)d_in[9];
    const float* g2   = (const float*)d_in[10];
    const float* b2   = (const float*)d_in[11];
    const float* wf1  = (const float*)d_in[12];
    const float* bf1  = (const float*)d_in[13];
    const float* wf2  = (const float*)d_in[14];
    const float* bf2  = (const float*)d_in[15];
    float* out = (float*)d_out;

    bf16 *p_h, *p_qkvb, *p_y2b, *p_u, *p_wtqkv, *p_wtf1, *p_wtf2;
    float *p_att, *p_y2f, *p_bqkv;
    cudaGetSymbolAddress((void**)&p_h,     g_h);
    cudaGetSymbolAddress((void**)&p_qkvb,  g_qkvb);
    cudaGetSymbolAddress((void**)&p_att,   g_att);
    cudaGetSymbolAddress((void**)&p_y2f,   g_y2f);
    cudaGetSymbolAddress((void**)&p_y2b,   g_y2b);
    cudaGetSymbolAddress((void**)&p_u,     g_u);
    cudaGetSymbolAddress((void**)&p_wtqkv, g_wt_qkv);
    cudaGetSymbolAddress((void**)&p_wtf1,  g_wt_f1);
    cudaGetSymbolAddress((void**)&p_wtf2,  g_wt_f2);
    cudaGetSymbolAddress((void**)&p_bqkv,  g_bqkv);

    cudaFuncSetAttribute(tgemm<false, false, true >, cudaFuncAttributeMaxDynamicSharedMemorySize, SMEM2);
    cudaFuncSetAttribute(tgemm<true,  false, true >, cudaFuncAttributeMaxDynamicSharedMemorySize, SMEM2);
    cudaFuncSetAttribute(tgemm<false, true,  false>, cudaFuncAttributeMaxDynamicSharedMemorySize, SMEM2);

    // 1. weight pack (launch #1)
    pack_all<<<705, dim3(32, 8)>>>(wq, wk, wv, wf1, wf2, bq, bk, bv,
                                   p_wtqkv, p_wtf1, p_wtf2, p_bqkv);

    // 2. LN1 + shift + window partition (launch #2)
    ln1_window_kernel<<<MTOK / 8, 256>>>(x, g1, b1, p_h);

    // 3. fused QKV projection, bf16 out (launch #3)
    tgemm<false, false, true><<<dim3(768 / 128, MTOK / 128), 128, SMEM2>>>(
        p_h, p_wtqkv, p_bqkv, nullptr, p_qkvb, MTOK, 768, CD);

    // 4. tensor-core windowed attention (launch #4)
    attn_mma<<<NWIN * 4, 256>>>(p_qkvb, tbl, p_att);

    // 5. reverse window/roll + residual + LN2 (launch #5)
    unwin_res_ln2<<<MTOK / 8, 256>>>(x, p_att, g2, b2, p_y2f, p_y2b);

    // 6. fc1 + exact GELU, bf16 out (launch #6)
    tgemm<true, false, true><<<dim3(HIDDEN / 128, MTOK / 128), 128, SMEM2>>>(
        p_y2b, p_wtf1, bf1, nullptr, p_u, MTOK, HIDDEN, CD);

    // 7. fc2 + residual, fp32 final (launch #7)
    tgemm<false, true, false><<<dim3(CD / 128, MTOK / 128), 128, SMEM2>>>(
        p_u, p_wtf2, bf2, p_y2f, out, MTOK, CD, HIDDEN);
}

// round 17
// speedup vs baseline: 1.0272x; 1.0272x over previous
#include <cuda_runtime.h>
#include <cuda_bf16.h>
#include <math.h>
#include <stdint.h>

typedef __nv_bfloat16 bf16;

// Problem constants (B=2, H=W=256, C=256, NH=8, WS=8, SHIFT=4)
#define MTOK   131072
#define CD     256
#define NWIN   2048
#define HIDDEN 1024

// ---------------- static scratch ----------------
__device__ __align__(16) bf16  g_h   [(size_t)MTOK * CD];       // LN1 out (bf16 GEMM A)
__device__ __align__(16) bf16  g_qkvb[(size_t)MTOK * 768];      // fused QKV out (bf16)
__device__ float g_att [(size_t)MTOK * CD];                     // attn out
__device__ float g_y2f [(size_t)MTOK * CD];                     // LN2 out fp32 (residual)
__device__ __align__(16) bf16  g_y2b [(size_t)MTOK * CD];       // LN2 out bf16 (GEMM A)
__device__ __align__(16) bf16  g_u   [(size_t)MTOK * HIDDEN];   // fc1+gelu out (bf16)
__device__ __align__(16) bf16 g_wt_qkv[768 * 256];
__device__ __align__(16) bf16 g_wt_f1 [1024 * 256];
__device__ __align__(16) bf16 g_wt_f2 [256 * 1024];
__device__ float g_bqkv[768];

__device__ __forceinline__ uint32_t pkbf(float a, float b) {
    __nv_bfloat162 t = __floats2bfloat162_rn(a, b);
    return reinterpret_cast<uint32_t&>(t);
}
__device__ __forceinline__ uint32_t smem_u32(const void* p) {
    return (uint32_t)__cvta_generic_to_shared(p);
}

// ---------------- single weight-pack kernel (transposes + bias), 705 blocks --------------
__device__ __forceinline__ void tr_tile(const float* __restrict__ src, bf16* __restrict__ dst,
                                        int R, int Cc, int bx, int by) {
    __shared__ float t[32][33];
    int x = bx * 32 + threadIdx.x;
#pragma unroll
    for (int i = 0; i < 32; i += 8) {
        int y = by * 32 + threadIdx.y + i;
        t[threadIdx.y + i][threadIdx.x] = src[(size_t)y * Cc + x];
    }
    __syncthreads();
    int x2 = by * 32 + threadIdx.x;
#pragma unroll
    for (int i = 0; i < 32; i += 8) {
        int y2 = bx * 32 + threadIdx.y + i;
        dst[(size_t)y2 * R + x2] = __float2bfloat16_rn(t[threadIdx.x][threadIdx.y + i]);
    }
}

__global__ void pack_all(const float* __restrict__ wq, const float* __restrict__ wk,
                         const float* __restrict__ wv, const float* __restrict__ wf1,
                         const float* __restrict__ wf2,
                         const float* __restrict__ bq, const float* __restrict__ bk,
                         const float* __restrict__ bv,
                         bf16* __restrict__ wtqkv, bf16* __restrict__ wtf1,
                         bf16* __restrict__ wtf2, float* __restrict__ bqkv) {
    int b = blockIdx.x;
    if (b < 64) {
        tr_tile(wq, wtqkv, 256, 256, b & 7, b >> 3);
    } else if (b < 128) {
        int t = b - 64;  tr_tile(wk, wtqkv + 65536, 256, 256, t & 7, t >> 3);
    } else if (b < 192) {
        int t = b - 128; tr_tile(wv, wtqkv + 131072, 256, 256, t & 7, t >> 3);
    } else if (b < 448) {
        int t = b - 192; tr_tile(wf1, wtf1, 256, 1024, t & 31, t >> 5);
    } else if (b < 704) {
        int t = b - 448; tr_tile(wf2, wtf2, 1024, 256, t & 7, t >> 3);
    } else {
        int t = threadIdx.y * 32 + threadIdx.x;
        bqkv[t]       = bq[t];
        bqkv[256 + t] = bk[t];
        bqkv[512 + t] = bv[t];
    }
}

// ---------------- warp-level dual reduction ----------------
__device__ __forceinline__ void warpReduce2(float& a, float& b) {
#pragma unroll
    for (int o = 16; o; o >>= 1) {
        a += __shfl_xor_sync(0xffffffffu, a, o);
        b += __shfl_xor_sync(0xffffffffu, b, o);
    }
}

// ---------------- kernel 1: LN1 + shift-roll + window partition (warp/row, bf16 out) -----
__global__ void ln1_window_kernel(const float* __restrict__ x,
                                  const float* __restrict__ g1,
                                  const float* __restrict__ b1,
                                  bf16* __restrict__ h) {
    int m = blockIdx.x * 8 + (threadIdx.x >> 5);
    int lane = threadIdx.x & 31;
    int bw = m >> 6, n = m & 63;
    int bb = bw >> 10, widx = bw & 1023;
    int wh = widx >> 5, ww = widx & 31;
    int r = n >> 3, c = n & 7;
    int gh = (wh * 8 + r + 4) & 255;
    int gw = (ww * 8 + c + 4) & 255;
    const float* row = x + ((size_t)bb * 65536 + (size_t)gh * 256 + gw) * CD;
    int ch = lane * 8;
    float4 v0 = *(const float4*)(row + ch);
    float4 v1 = *(const float4*)(row + ch + 4);
    float a = v0.x + v0.y + v0.z + v0.w + v1.x + v1.y + v1.z + v1.w;
    float b = v0.x * v0.x + v0.y * v0.y + v0.z * v0.z + v0.w * v0.w
            + v1.x * v1.x + v1.y * v1.y + v1.z * v1.z + v1.w * v1.w;
    warpReduce2(a, b);
    float mu = a * (1.0f / CD);
    float rstd = rsqrtf(b * (1.0f / CD) - mu * mu + 1e-5f);
    float4 ga = *(const float4*)(g1 + ch);
    float4 gb = *(const float4*)(g1 + ch + 4);
    float4 ba = *(const float4*)(b1 + ch);
    float4 bbv = *(const float4*)(b1 + ch + 4);
    uint4 st;
    st.x = pkbf((v0.x - mu) * rstd * ga.x + ba.x,  (v0.y - mu) * rstd * ga.y + ba.y);
    st.y = pkbf((v0.z - mu) * rstd * ga.z + ba.z,  (v0.w - mu) * rstd * ga.w + ba.w);
    st.z = pkbf((v1.x - mu) * rstd * gb.x + bbv.x, (v1.y - mu) * rstd * gb.y + bbv.y);
    st.w = pkbf((v1.z - mu) * rstd * gb.z + bbv.z, (v1.w - mu) * rstd * gb.w + bbv.w);
    *(uint4*)(h + (size_t)m * CD + ch) = st;
}

// ---------------- mma/ldmatrix primitives ----------------
__device__ __forceinline__ void ldsm4(uint32_t& r0, uint32_t& r1, uint32_t& r2, uint32_t& r3,
                                      uint32_t addr) {
    asm volatile("ldmatrix.sync.aligned.m8n8.x4.shared.b16 {%0,%1,%2,%3}, [%4];"
                 : "=r"(r0), "=r"(r1), "=r"(r2), "=r"(r3) : "r"(addr));
}
__device__ __forceinline__ void ldsm4t(uint32_t& r0, uint32_t& r1, uint32_t& r2, uint32_t& r3,
                                       uint32_t addr) {
    asm volatile("ldmatrix.sync.aligned.m8n8.x4.trans.shared.b16 {%0,%1,%2,%3}, [%4];"
                 : "=r"(r0), "=r"(r1), "=r"(r2), "=r"(r3) : "r"(addr));
}
__device__ __forceinline__ void mma_bf16(float* c, const uint32_t* a, const uint32_t* b) {
    asm volatile(
        "mma.sync.aligned.m16n8k16.row.col.f32.bf16.bf16.f32 "
        "{%0,%1,%2,%3}, {%4,%5,%6,%7}, {%8,%9}, {%0,%1,%2,%3};"
        : "+f"(c[0]), "+f"(c[1]), "+f"(c[2]), "+f"(c[3])
        : "r"(a[0]), "r"(a[1]), "r"(a[2]), "r"(a[3]), "r"(b[0]), "r"(b[1]));
}
#define CP_COMMIT() asm volatile("cp.async.commit_group;")

// ---------------- bf16 tensor-core GEMM, cp.async 3-stage, BK=64, 2 CTAs/SM -------------
// (round-12 proven configuration: 256 threads, 8 warps 4m x 2n, warp tile 32x64)
#define ROWB 144                       // 128B data + 16B pad: LDSM conflict-free
#define OPBYTES (128 * ROWB)
#define STG_BYTES (2 * OPBYTES)
#define STAGES 3
#define SMEM_BYTES (STAGES * STG_BYTES)

__device__ __forceinline__ void fill_stage(uint32_t sA, uint32_t sB,
                                           const bf16* __restrict__ A,
                                           const bf16* __restrict__ Bt,
                                           int m0, int n0, int K, int k0, int tid) {
#pragma unroll
    for (int i = 0; i < 4; i++) {
        int idx = tid + 256 * i;
        int rm = idx >> 3, g = idx & 7;
        uint32_t doff = (uint32_t)(rm * ROWB + g * 16);
        const bf16* ga = A + (size_t)(m0 + rm) * K + k0 + g * 8;
        asm volatile("cp.async.cg.shared.global [%0], [%1], 16;" :: "r"(sA + doff), "l"(ga));
        const bf16* gb = Bt + (size_t)(n0 + rm) * K + k0 + g * 8;
        asm volatile("cp.async.cg.shared.global [%0], [%1], 16;" :: "r"(sB + doff), "l"(gb));
    }
}

template <bool GELU, bool RES, bool OUTBF>
__global__ void __launch_bounds__(256, 2)
tgemm(const bf16* __restrict__ A, const bf16* __restrict__ Bt,
      const float* __restrict__ bias, const float* __restrict__ res,
      void* __restrict__ Cout, int M, int Nn, int K) {
    extern __shared__ __align__(16) char smem[];
    int tid = threadIdx.x;
    int lane = tid & 31, wid = tid >> 5;
    int wm = wid >> 1, wn = wid & 1;
    int m0 = blockIdx.y * 128, n0 = blockIdx.x * 128;
    uint32_t base = (uint32_t)__cvta_generic_to_shared(smem);

    float acc[2][8][4] = {};
    const int NITER = K >> 6;

#pragma unroll
    for (int s = 0; s < STAGES - 1; s++) {
        if (s < NITER) {
            uint32_t sA = base + s * STG_BYTES;
            fill_stage(sA, sA + OPBYTES, A, Bt, m0, n0, K, s * 64, tid);
        }
        CP_COMMIT();
    }

    int l7 = lane & 7, lh = (lane >> 3) & 1, ls = lane >> 4;
    for (int it = 0; it < NITER; it++) {
        asm volatile("cp.async.wait_group %0;" :: "n"(STAGES - 2));
        __syncthreads();

        int nxt = it + STAGES - 1;
        if (nxt < NITER) {
            uint32_t sA = base + (nxt % STAGES) * STG_BYTES;
            fill_stage(sA, sA + OPBYTES, A, Bt, m0, n0, K, nxt * 64, tid);
        }
        CP_COMMIT();

        uint32_t sA = base + (it % STAGES) * STG_BYTES;
        uint32_t sB = sA + OPBYTES;
#pragma unroll
        for (int kk = 0; kk < 4; kk++) {
            uint32_t af[2][4];
#pragma unroll
            for (int mt = 0; mt < 2; mt++) {
                int row = wm * 32 + mt * 16 + l7 + lh * 8;
                ldsm4(af[mt][0], af[mt][1], af[mt][2], af[mt][3],
                      sA + (uint32_t)(row * ROWB + kk * 32 + ls * 16));
            }
            uint32_t bfr[4][4];
#pragma unroll
            for (int p = 0; p < 4; p++) {
                int row = wn * 64 + p * 16 + l7 + ls * 8;
                ldsm4(bfr[p][0], bfr[p][1], bfr[p][2], bfr[p][3],
                      sB + (uint32_t)(row * ROWB + kk * 32 + lh * 16));
            }
#pragma unroll
            for (int mt = 0; mt < 2; mt++)
#pragma unroll
                for (int p = 0; p < 4; p++) {
                    mma_bf16(acc[mt][2 * p],     af[mt], &bfr[p][0]);
                    mma_bf16(acc[mt][2 * p + 1], af[mt], &bfr[p][2]);
                }
        }
        __syncthreads();
    }

    int r0 = lane >> 2, c0 = (lane & 3) << 1;
#pragma unroll
    for (int mt = 0; mt < 2; mt++) {
#pragma unroll
        for (int half = 0; half < 2; half++) {
            int row = m0 + wm * 32 + mt * 16 + half * 8 + r0;
#pragma unroll
            for (int nt = 0; nt < 8; nt++) {
                int col = n0 + wn * 64 + ((nt >> 1) << 4) + ((nt & 1) << 3) + c0;
                float v0 = acc[mt][nt][half * 2 + 0] + bias[col];
                float v1 = acc[mt][nt][half * 2 + 1] + bias[col + 1];
                if (GELU) {
                    v0 = 0.5f * v0 * (1.0f + erff(v0 * 0.70710678118654752f));
                    v1 = 0.5f * v1 * (1.0f + erff(v1 * 0.70710678118654752f));
                }
                if (RES) {
                    v0 += res[(size_t)row * Nn + col];
                    v1 += res[(size_t)row * Nn + col + 1];
                }
                if (OUTBF) {
                    *(uint32_t*)((bf16*)Cout + (size_t)row * Nn + col) = pkbf(v0, v1);
                } else {
                    *(float2*)((float*)Cout + (size_t)row * Nn + col) = make_float2(v0, v1);
                }
            }
        }
    }
}

// ---------------- kernel 3: tensor-core windowed attention ----------------
// block = (window, 2-head group), 256 threads = 8 warps; warp = (head, 16-row Q quarter)
__global__ void __launch_bounds__(256, 3)
attn_mma(const bf16* __restrict__ qkv, const float* __restrict__ bias_table,
         float* __restrict__ attn_out) {
    __shared__ __align__(16) bf16 sQ[2][64][40];   // 80B rows: conflict-free LDSM
    __shared__ __align__(16) bf16 sK[2][64][40];
    __shared__ __align__(16) bf16 sV[2][64][40];
    __shared__ float sbias[1800];                   // 225 x 8
    __shared__ int   lab[64];

    int tid = threadIdx.x;
    int bw = blockIdx.x >> 2, hg = blockIdx.x & 3;  // head group: heads hg*2, hg*2+1
    int widx = bw & 1023;
    int wh = widx >> 5, ww = widx & 31;

#pragma unroll
    for (int i = 0; i < 6; i++) {
        int idx = tid + 256 * i;                    // 0..1535
        int nm = idx >> 3;
        int hc = idx & 7;
        int n = nm / 3, m = nm - 3 * n;
        const bf16* src = qkv + (size_t)(bw * 64 + n) * 768 + m * 256 + hg * 64 + hc * 8;
        uint4 val = *(const uint4*)src;
        bf16* dst = (m == 0 ? &sQ[0][0][0] : (m == 1 ? &sK[0][0][0] : &sV[0][0][0]));
        int h = hc >> 2, c = hc & 3;
        *(uint4*)(dst + (h * 64 + n) * 40 + c * 8) = val;
    }
    for (int j = tid; j < 1800; j += 256) sbias[j] = bias_table[j];
    if (tid < 64) {
        int ri2 = tid >> 3, ci2 = tid & 7;
        int srow = wh * 8 + ri2, scol = ww * 8 + ci2;
        int lh2 = (srow < 248) ? 0 : ((srow < 252) ? 1 : 2);
        int lw2 = (scol < 248) ? 0 : ((scol < 252) ? 1 : 2);
        lab[tid] = lh2 * 3 + lw2;
    }
    __syncthreads();

    int lane = tid & 31, wid = tid >> 5;
    int h = wid & 1, mq = wid >> 1;
    int m0 = mq * 16;
    int headg = hg * 2 + h;
    const bf16* Qh = &sQ[h][0][0];
    const bf16* Kh = &sK[h][0][0];
    const bf16* Vh = &sV[h][0][0];

    uint32_t aq[2][4];
    {
        int row = m0 + (lane & 15);
        int col = (lane >> 4) * 8;
#pragma unroll
        for (int kt = 0; kt < 2; kt++)
            ldsm4(aq[kt][0], aq[kt][1], aq[kt][2], aq[kt][3],
                  smem_u32(Qh + row * 40 + kt * 16 + col));
    }

    float S[8][4] = {};
    {
        int rofs = (lane & 7) + ((lane & 16) ? 8 : 0);
        int cofs = (lane & 8) ? 8 : 0;
#pragma unroll
        for (int nj = 0; nj < 4; nj++) {
#pragma unroll
            for (int dh = 0; dh < 2; dh++) {
                uint32_t kb[4];
                ldsm4(kb[0], kb[1], kb[2], kb[3],
                      smem_u32(Kh + (16 * nj + rofs) * 40 + dh * 16 + cofs));
                mma_bf16(S[2 * nj],     aq[dh], &kb[0]);
                mma_bf16(S[2 * nj + 1], aq[dh], &kb[2]);
            }
        }
    }

    const float sscale = 0.17677669529663687f;
    int g = lane >> 2, t = lane & 3;
    int i0 = m0 + g;
    int li[2] = { lab[i0], lab[i0 + 8] };
    int ri[2] = { i0 >> 3, (i0 + 8) >> 3 };
    int ci = i0 & 7;
#pragma unroll
    for (int n8 = 0; n8 < 8; n8++) {
#pragma unroll
        for (int e = 0; e < 4; e++) {
            int half = e >> 1;
            int j = n8 * 8 + t * 2 + (e & 1);
            int rj = j >> 3, cj = j & 7;
            int rel = (ri[half] - rj + 7) * 15 + (ci - cj + 7);
            float s = S[n8][e] * sscale + sbias[rel * 8 + headg];
            if (li[half] != lab[j]) s -= 100.0f;
            S[n8][e] = s;
        }
    }

    float mx0 = -1e30f, mx1 = -1e30f;
#pragma unroll
    for (int n8 = 0; n8 < 8; n8++) {
        mx0 = fmaxf(mx0, fmaxf(S[n8][0], S[n8][1]));
        mx1 = fmaxf(mx1, fmaxf(S[n8][2], S[n8][3]));
    }
    mx0 = fmaxf(mx0, __shfl_xor_sync(0xffffffffu, mx0, 1));
    mx0 = fmaxf(mx0, __shfl_xor_sync(0xffffffffu, mx0, 2));
    mx1 = fmaxf(mx1, __shfl_xor_sync(0xffffffffu, mx1, 1));
    mx1 = fmaxf(mx1, __shfl_xor_sync(0xffffffffu, mx1, 2));
    float s0 = 0.f, s1 = 0.f;
#pragma unroll
    for (int n8 = 0; n8 < 8; n8++) {
        S[n8][0] = __expf(S[n8][0] - mx0); s0 += S[n8][0];
        S[n8][1] = __expf(S[n8][1] - mx0); s0 += S[n8][1];
        S[n8][2] = __expf(S[n8][2] - mx1); s1 += S[n8][2];
        S[n8][3] = __expf(S[n8][3] - mx1); s1 += S[n8][3];
    }
    s0 += __shfl_xor_sync(0xffffffffu, s0, 1);
    s0 += __shfl_xor_sync(0xffffffffu, s0, 2);
    s1 += __shfl_xor_sync(0xffffffffu, s1, 1);
    s1 += __shfl_xor_sync(0xffffffffu, s1, 2);
    float inv0 = 1.0f / s0, inv1 = 1.0f / s1;
#pragma unroll
    for (int n8 = 0; n8 < 8; n8++) {
        S[n8][0] *= inv0; S[n8][1] *= inv0;
        S[n8][2] *= inv1; S[n8][3] *= inv1;
    }

    float O[4][4] = {};
    {
        int rofs2 = (lane & 7) + ((lane & 8) ? 8 : 0);
        int cofs2 = (lane & 16) ? 8 : 0;
#pragma unroll
        for (int kt = 0; kt < 4; kt++) {
            uint32_t pa[4];
            pa[0] = pkbf(S[2 * kt][0],     S[2 * kt][1]);
            pa[1] = pkbf(S[2 * kt][2],     S[2 * kt][3]);
            pa[2] = pkbf(S[2 * kt + 1][0], S[2 * kt + 1][1]);
            pa[3] = pkbf(S[2 * kt + 1][2], S[2 * kt + 1][3]);
#pragma unroll
            for (int dh = 0; dh < 2; dh++) {
                uint32_t vb[4];
                ldsm4t(vb[0], vb[1], vb[2], vb[3],
                       smem_u32(Vh + (16 * kt + rofs2) * 40 + dh * 16 + cofs2));
                mma_bf16(O[dh * 2],     pa, &vb[0]);
                mma_bf16(O[dh * 2 + 1], pa, &vb[2]);
            }
        }
    }

    size_t base = ((size_t)(bw * 8 + headg) * 64) * 32;
#pragma unroll
    for (int dn = 0; dn < 4; dn++) {
        int d = dn * 8 + t * 2;
        *(float2*)&attn_out[base + (size_t)i0 * 32 + d]       = make_float2(O[dn][0], O[dn][1]);
        *(float2*)&attn_out[base + (size_t)(i0 + 8) * 32 + d] = make_float2(O[dn][2], O[dn][3]);
    }
}

// ---------------- kernel 4: un-window + un-roll + residual + LN2 (warp/row) -------------
__global__ void unwin_res_ln2(const float* __restrict__ x, const float* __restrict__ att,
                              const float* __restrict__ g2, const float* __restrict__ b2,
                              float* __restrict__ y2f, bf16* __restrict__ y2b) {
    int m = blockIdx.x * 8 + (threadIdx.x >> 5);
    int lane = threadIdx.x & 31;
    int bb = m >> 16, l = m & 65535;
    int gh = l >> 8, gw = l & 255;
    int sh = (gh + 252) & 255, sw = (gw + 252) & 255;
    int wh = sh >> 3, r = sh & 7, ww = sw >> 3, c = sw & 7;
    size_t base = ((size_t)((bb * 1024 + wh * 32 + ww) * 8 + r) * 64 + (size_t)c * 8) * 32;
    int ch = lane * 8;
    const float* xr = x + (size_t)m * CD + ch;
    const float* ar = att + base + ch;
    float4 x0 = *(const float4*)xr;
    float4 x1 = *(const float4*)(xr + 4);
    float4 a0 = *(const float4*)ar;
    float4 a1 = *(const float4*)(ar + 4);
    float4 v0 = {x0.x + a0.x, x0.y + a0.y, x0.z + a0.z, x0.w + a0.w};
    float4 v1 = {x1.x + a1.x, x1.y + a1.y, x1.z + a1.z, x1.w + a1.w};
    float a = v0.x + v0.y + v0.z + v0.w + v1.x + v1.y + v1.z + v1.w;
    float b = v0.x * v0.x + v0.y * v0.y + v0.z * v0.z + v0.w * v0.w
            + v1.x * v1.x + v1.y * v1.y + v1.z * v1.z + v1.w * v1.w;
    warpReduce2(a, b);
    float mu = a * (1.0f / CD);
    float rstd = rsqrtf(b * (1.0f / CD) - mu * mu + 1e-5f);
    float4 ga = *(const float4*)(g2 + ch);
    float4 gb = *(const float4*)(g2 + ch + 4);
    float4 ba = *(const float4*)(b2 + ch);
    float4 bbv = *(const float4*)(b2 + ch + 4);
    float4 o0, o1;
    o0.x = (v0.x - mu) * rstd * ga.x + ba.x;
    o0.y = (v0.y - mu) * rstd * ga.y + ba.y;
    o0.z = (v0.z - mu) * rstd * ga.z + ba.z;
    o0.w = (v0.w - mu) * rstd * ga.w + ba.w;
    o1.x = (v1.x - mu) * rstd * gb.x + bbv.x;
    o1.y = (v1.y - mu) * rstd * gb.y + bbv.y;
    o1.z = (v1.z - mu) * rstd * gb.z + bbv.z;
    o1.w = (v1.w - mu) * rstd * gb.w + bbv.w;
    float* dstf = y2f + (size_t)m * CD + ch;
    *(float4*)dstf = o0;
    *(float4*)(dstf + 4) = o1;
    uint4 st = { pkbf(o0.x, o0.y), pkbf(o0.z, o0.w), pkbf(o1.x, o1.y), pkbf(o1.z, o1.w) };
    *(uint4*)(y2b + (size_t)m * CD + ch) = st;
}

// ---------------- host launch ----------------
extern "C" void kernel_launch(void* const* d_in, const int* in_sizes, int n_in,
                              void* d_out, int out_size) {
    (void)in_sizes; (void)n_in; (void)out_size;
    const float* x    = (const float*)d_in[0];
    const float* g1   = (const float*)d_in[1];
    const float* b1   = (const float*)d_in[2];
    const float* wq   = (const float*)d_in[3];
    const float* bq   = (const float*)d_in[4];
    const float* wk   = (const float*)d_in[5];
    const float* bk   = (const float*)d_in[6];
    const float* wv   = (const float*)d_in[7];
    const float* bv   = (const float*)d_in[8];
    const float* tbl  = (const float*)d_in[9];
    const float* g2   = (const float*)d_in[10];
    const float* b2   = (const float*)d_in[11];
    const float* wf1  = (const float*)d_in[12];
    const float* bf1  = (const float*)d_in[13];
    const float* wf2  = (const float*)d_in[14];
    const float* bf2  = (const float*)d_in[15];
    float* out = (float*)d_out;

    bf16 *p_h, *p_qkvb, *p_y2b, *p_u, *p_wtqkv, *p_wtf1, *p_wtf2;
    float *p_att, *p_y2f, *p_bqkv;
    cudaGetSymbolAddress((void**)&p_h,     g_h);
    cudaGetSymbolAddress((void**)&p_qkvb,  g_qkvb);
    cudaGetSymbolAddress((void**)&p_att,   g_att);
    cudaGetSymbolAddress((void**)&p_y2f,   g_y2f);
    cudaGetSymbolAddress((void**)&p_y2b,   g_y2b);
    cudaGetSymbolAddress((void**)&p_u,     g_u);
    cudaGetSymbolAddress((void**)&p_wtqkv, g_wt_qkv);
    cudaGetSymbolAddress((void**)&p_wtf1,  g_wt_f1);
    cudaGetSymbolAddress((void**)&p_wtf2,  g_wt_f2);
    cudaGetSymbolAddress((void**)&p_bqkv,  g_bqkv);

    cudaFuncSetAttribute(tgemm<false, false, true >, cudaFuncAttributeMaxDynamicSharedMemorySize, SMEM_BYTES);
    cudaFuncSetAttribute(tgemm<true,  false, true >, cudaFuncAttributeMaxDynamicSharedMemorySize, SMEM_BYTES);
    cudaFuncSetAttribute(tgemm<false, true,  false>, cudaFuncAttributeMaxDynamicSharedMemorySize, SMEM_BYTES);

    // 1. weight pack (launch #1)
    pack_all<<<705, dim3(32, 8)>>>(wq, wk, wv, wf1, wf2, bq, bk, bv,
                                   p_wtqkv, p_wtf1, p_wtf2, p_bqkv);

    // 2. LN1 + shift + window partition (launch #2)
    ln1_window_kernel<<<MTOK / 8, 256>>>(x, g1, b1, p_h);

    // 3. fused QKV projection, bf16 out (launch #3)
    tgemm<false, false, true><<<dim3(768 / 128, MTOK / 128), 256, SMEM_BYTES>>>(
        p_h, p_wtqkv, p_bqkv, nullptr, p_qkvb, MTOK, 768, CD);

    // 4. tensor-core windowed attention (launch #4)
    attn_mma<<<NWIN * 4, 256>>>(p_qkvb, tbl, p_att);

    // 5. reverse window/roll + residual + LN2 (launch #5)
    unwin_res_ln2<<<MTOK / 8, 256>>>(x, p_att, g2, b2, p_y2f, p_y2b);

    // 6. fc1 + exact GELU, bf16 out (launch #6)
    tgemm<true, false, true><<<dim3(HIDDEN / 128, MTOK / 128), 256, SMEM_BYTES>>>(
        p_y2b, p_wtf1, bf1, nullptr, p_u, MTOK, HIDDEN, CD);

    // 7. fc2 + residual, fp32 final (launch #7)
    tgemm<false, true, false><<<dim3(CD / 128, MTOK / 128), 256, SMEM_BYTES>>>(
        p_u, p_wtf2, bf2, p_y2f, out, MTOK, CD, HIDDEN);
}